// round 11
// baseline (speedup 1.0000x reference)
#include <cuda_runtime.h>
#include <cuda_bf16.h>

// Upscale_15358803050749: upfirdn2d up=2, 4x4 kernel [1,3,3,1]^2, gain 4.
// x: (8,128,128,128) f32 -> out: (8,128,256,256) f32.
//
// Polyphase (reference's dilated conv, pad0=2), separably factored:
//   K[v][u] = C[v]*D[u],  D[u]=K[0][u],  C[v]=K[v][0]/K[0][0]  (C0==1)
//
// R11 = R9 structure (2 input rows -> 4 out rows per work unit, intra-warp
// smem halo exchange, wrapped lane-31 outputs) but each thread processes
// TWO independent work units: same (ry, lane) window in planes pl and
// pl+512. All 8 LDG.128 issued up front (MLP=8); weights/masks/addresses
// shared. Tests the latency-bound hypothesis at constant per-byte traffic.

#define W_IN   128
#define H_IN   128
#define W_OUT  256
#define NPL    512           // planes per unit-set (NC=1024 total)
#define DRP    64            // thread-rows per plane (2 input rows each)
#define PLSTR  (H_IN * W_IN) // plane stride (in)
#define OPSTR  (256 * W_OUT) // plane stride (out)

__global__ __launch_bounds__(128, 8)
void Upscale_15358803050749_kernel(const float* __restrict__ x,
                                   const float* __restrict__ k,
                                   float* __restrict__ out) {
    __shared__ float4 sm[4][8][32];       // 4 warps x (4 rows x 2 units) x 32

    int t    = blockIdx.x * blockDim.x + threadIdx.x;
    int lane = t & 31;
    int wid  = (threadIdx.x >> 5) & 3;
    int rp   = t >> 5;
    int ry   = rp & (DRP - 1);
    int pl   = rp >> 6;                   // plane 0..NPL-1 (unit A)
    int iy0  = ry * 2;
    int ix0  = lane * 4;

    const float* xpA = x + pl * PLSTR;
    const float* xpB = xpA + NPL * PLSTR;
    float* opA = out + pl * OPSTR;
    float* opB = opA + NPL * OPSTR;

    // shared row offsets + validity (identical for both units)
    bool vm = (iy0 > 0);
    bool vc = (iy0 + 2 < H_IN);
    int om = (vm ? (iy0 - 1) : 0) * W_IN + ix0;
    int oa = iy0 * W_IN + ix0;
    int ob = oa + W_IN;
    int oc = (vc ? (iy0 + 2) : 0) * W_IN + ix0;

    // ---- 8 independent vector loads, both units, up front (MLP=8) ----
    float4 VmA = *reinterpret_cast<const float4*>(xpA + om);
    float4 VaA = *reinterpret_cast<const float4*>(xpA + oa);
    float4 VbA = *reinterpret_cast<const float4*>(xpA + ob);
    float4 VcA = *reinterpret_cast<const float4*>(xpA + oc);
    float4 VmB = *reinterpret_cast<const float4*>(xpB + om);
    float4 VaB = *reinterpret_cast<const float4*>(xpB + oa);
    float4 VbB = *reinterpret_cast<const float4*>(xpB + ob);
    float4 VcB = *reinterpret_cast<const float4*>(xpB + oc);

    // ---- separable factors (overlaps load latency) ----
    float D0 = __ldg(k + 0), D1 = __ldg(k + 1), D2 = __ldg(k + 2), D3 = __ldg(k + 3);
    float inv = 1.0f / D0;
    float C1 = __ldg(k + 4)  * inv;
    float C2 = __ldg(k + 8)  * inv;
    float C3 = __ldg(k + 12) * inv;     // C0 == 1

    // ---- stage both units, one syncwarp ----
    sm[wid][0][lane] = VmA;  sm[wid][1][lane] = VaA;
    sm[wid][2][lane] = VbA;  sm[wid][3][lane] = VcA;
    sm[wid][4][lane] = VmB;  sm[wid][5][lane] = VaB;
    sm[wid][6][lane] = VbB;  sm[wid][7][lane] = VcB;
    __syncwarp();

    int ln = (lane + 1) & 31;             // lane 31 wraps to lane 0 (= x[0..3])
    float zm = vm ? 1.f : 0.f;
    float zc = vc ? 1.f : 0.f;
    bool last = (lane == 31);
    int cA = 8 * lane + 4;                 // out cols [8l+4..8l+7]
    int cB = (8 * lane + 8) & (W_OUT - 1); // [8l+8..8l+11] (lane31 -> 0..3)

    // ---- per-unit compute + store (macro over unit index/base) ----
    #define DO_UNIT(U, Vm_, Va_, Vb_, Vc_, OP)                                \
    {                                                                         \
        float4 Nm = sm[wid][4*(U)+0][ln];                                     \
        float4 Na = sm[wid][4*(U)+1][ln];                                     \
        float4 Nb = sm[wid][4*(U)+2][ln];                                     \
        float4 Nc = sm[wid][4*(U)+3][ln];                                     \
        float m6[6] = { Vm_.y*zm, Vm_.z*zm, Vm_.w*zm, Nm.x*zm, Nm.y*zm, Nm.z*zm }; \
        float a6[6] = { Va_.y, Va_.z, Va_.w, Na.x, Na.y, Na.z };              \
        float b6[6] = { Vb_.y, Vb_.z, Vb_.w, Nb.x, Nb.y, Nb.z };              \
        float c6[6] = { Vc_.y*zc, Vc_.z*zc, Vc_.w*zc, Nc.x*zc, Nc.y*zc, Nc.z*zc }; \
        float E0[6], O1[6], E2[6], O3[6];                                     \
        _Pragma("unroll")                                                     \
        for (int j = 0; j < 6; j++) {                                         \
            E0[j] = C3 * m6[j] + C1 * a6[j];                                  \
            O1[j] = C2 * a6[j] + b6[j];                                       \
            E2[j] = C3 * a6[j] + C1 * b6[j];                                  \
            O3[j] = C2 * b6[j] + c6[j];                                       \
        }                                                                     \
        float* q0 = (OP) + (2 * iy0) * W_OUT;                                 \
        _Pragma("unroll")                                                     \
        for (int s = 0; s < 4; s++) {                                         \
            const float* T = (s == 0) ? E0 : (s == 1) ? O1 : (s == 2) ? E2 : O3; \
            float w2z = last ? 0.f : T[2];                                    \
            float x3z = last ? 0.f : T[3];                                    \
            float o0 = D3*T[0] + D1*T[1];                                     \
            float o1 = D2*T[1] + D0*T[2];                                     \
            float o2 = D3*T[1] + D1*T[2];                                     \
            float o3 = D2*T[2] + D0*x3z;                                      \
            float o4 = D3*w2z  + D1*T[3];                                     \
            float o5 = D2*T[3] + D0*T[4];                                     \
            float o6 = D3*T[3] + D1*T[4];                                     \
            float o7 = D2*T[4] + D0*T[5];                                     \
            float* qr = q0 + s * W_OUT;                                       \
            __stcs(reinterpret_cast<float4*>(qr + cA), make_float4(o0,o1,o2,o3)); \
            __stcs(reinterpret_cast<float4*>(qr + cB), make_float4(o4,o5,o6,o7)); \
        }                                                                     \
    }

    DO_UNIT(0, VmA, VaA, VbA, VcA, opA)
    DO_UNIT(1, VmB, VaB, VbB, VcB, opB)
    #undef DO_UNIT
}

extern "C" void kernel_launch(void* const* d_in, const int* in_sizes, int n_in,
                              void* d_out, int out_size) {
    const float* x = (const float*)d_in[0];   // (8,128,128,128)
    const float* k = (const float*)d_in[1];   // (4,4)
    float* out = (float*)d_out;               // (8,128,256,256)

    // warps = NPL * DRP = 32768 ; threads = 1,048,576 ; blocks = 8192 @ 128
    int threads = 128;
    int blocks = (NPL * DRP * 32) / threads;
    Upscale_15358803050749_kernel<<<blocks, threads>>>(x, k, out);
}

// round 12
// speedup vs baseline: 1.2251x; 1.2251x over previous
#include <cuda_runtime.h>
#include <cuda_bf16.h>

// Upscale_15358803050749: upfirdn2d up=2, 4x4 kernel [1,3,3,1]^2, gain 4.
// x: (8,128,128,128) f32 -> out: (8,128,256,256) f32.
//
// Polyphase (reference's dilated conv, pad0=2), separably factored:
//   K[v][u] = C[v]*D[u],  D[u]=K[0][u],  C[v]=K[v][0]/K[0][0]  (C0==1)
//   horiz: out col 2i   = D3*x[i-1] + D1*x[i]
//          out col 2i+1 = D2*x[i]   + D0*x[i+1]
//   vert : out row 2r   = C3*row(r-1) + C1*row(r)
//          out row 2r+1 = C2*row(r)   + row(r+1)
//
// R12: CONTIGUOUS STORES. Every previous round stored 16B-on/16B-off
// (lane l at byte 32l+16) => 2x store wavefronts + half-filled sectors.
// Fix: 2 input cols per thread -> exactly one float4 of output per row.
// A warp's STG.128 covers a contiguous 512B half-row. Two warps pair up
// per work unit (2 input rows -> 4 output rows, full 128-col width).
// Vertical combine happens in registers on own columns; the horizontal
// halo exchange (combined values) goes through block smem (float2 STS,
// scalar LDS halos, one __syncthreads).

#define W_IN   128
#define H_IN   128
#define W_OUT  256
#define NC     1024          // 8 * 128 planes
#define RYP    64            // row-units per plane (2 input rows each)

__global__ __launch_bounds__(128, 8)
void Upscale_15358803050749_kernel(const float* __restrict__ x,
                                   const float* __restrict__ k,
                                   float* __restrict__ out) {
    // 2 units per block x 4 out-rows x 128 combined values = 4KB
    __shared__ float sm[2][4][128];

    int tid   = threadIdx.x;
    int gw    = (blockIdx.x * blockDim.x + tid) >> 5;   // global warp
    int lane  = tid & 31;
    int ul    = tid >> 6;            // unit-local index within block (0..1)
    int half  = (tid >> 5) & 1;      // which half-row this warp covers
    int unit  = gw >> 1;             // global work unit (2 warps each)
    int ry    = unit & (RYP - 1);
    int pl    = unit >> 6;           // plane 0..NC-1
    int g     = half * 32 + lane;    // column group 0..63 (2 input cols each)
    int iy0   = ry * 2;
    int cx    = 2 * g;               // input col base

    const float* xp = x   + pl * (H_IN * W_IN);
    float*       op = out + pl * (256 * W_OUT);

    // ---- 4 independent LDG.64 (rows iy0-1 .. iy0+2), warp-contiguous ----
    bool vm = (iy0 > 0);
    bool vc = (iy0 + 2 < H_IN);
    const float* pm = xp + (vm ? (iy0 - 1) : 0) * W_IN + cx;
    const float* pa = xp + iy0 * W_IN + cx;
    const float* pb = pa + W_IN;
    const float* pc = xp + (vc ? (iy0 + 2) : 0) * W_IN + cx;

    float2 Vm = *reinterpret_cast<const float2*>(pm);
    float2 Va = *reinterpret_cast<const float2*>(pa);
    float2 Vb = *reinterpret_cast<const float2*>(pb);
    float2 Vc = *reinterpret_cast<const float2*>(pc);

    // ---- separable factors (overlaps load latency) ----
    float D0 = __ldg(k + 0), D1 = __ldg(k + 1), D2 = __ldg(k + 2), D3 = __ldg(k + 3);
    float inv = 1.0f / D0;
    float C1 = __ldg(k + 4)  * inv;
    float C2 = __ldg(k + 8)  * inv;
    float C3 = __ldg(k + 12) * inv;     // C0 == 1

    float zm = vm ? 1.f : 0.f;
    float zc = vc ? 1.f : 0.f;
    Vm.x *= zm; Vm.y *= zm;
    Vc.x *= zc; Vc.y *= zc;

    // ---- vertical combine on own 2 columns -> 4 out rows x 2 values ----
    float Tx[4], Ty[4];
    Tx[0] = C3 * Vm.x + C1 * Va.x;  Ty[0] = C3 * Vm.y + C1 * Va.y;  // row 2iy0
    Tx[1] = C2 * Va.x + Vb.x;       Ty[1] = C2 * Va.y + Vb.y;       // row 2iy0+1
    Tx[2] = C3 * Va.x + C1 * Vb.x;  Ty[2] = C3 * Va.y + C1 * Vb.y;  // row 2iy0+2
    Tx[3] = C2 * Vb.x + Vc.x;       Ty[3] = C2 * Vb.y + Vc.y;       // row 2iy0+3

    // ---- stage combined values (float2, conflict-free, contiguous) ----
    #pragma unroll
    for (int s = 0; s < 4; s++)
        *reinterpret_cast<float2*>(&sm[ul][s][cx]) = make_float2(Tx[s], Ty[s]);
    __syncthreads();

    // ---- horizontal transform + contiguous stores ----
    bool gl = (g > 0);
    bool gr = (g < 63);
    float* q = op + (2 * iy0) * W_OUT + 4 * g;   // 16B-aligned, warp-contig.
    #pragma unroll
    for (int s = 0; s < 4; s++) {
        float Tm1 = gl ? sm[ul][s][cx - 1] : 0.f;   // x[2g-1] (combined)
        float Tp2 = gr ? sm[ul][s][cx + 2] : 0.f;   // x[2g+2] (combined)
        float T0 = Tx[s], T1 = Ty[s];
        float o0 = D3 * Tm1 + D1 * T0;   // out col 4g   (even, i=2g)
        float o1 = D2 * T0  + D0 * T1;   // out col 4g+1 (odd)
        float o2 = D3 * T0  + D1 * T1;   // out col 4g+2 (even, i=2g+1)
        float o3 = D2 * T1  + D0 * Tp2;  // out col 4g+3 (odd)
        __stcs(reinterpret_cast<float4*>(q + s * W_OUT),
               make_float4(o0, o1, o2, o3));
    }
}

extern "C" void kernel_launch(void* const* d_in, const int* in_sizes, int n_in,
                              void* d_out, int out_size) {
    const float* x = (const float*)d_in[0];   // (8,128,128,128)
    const float* k = (const float*)d_in[1];   // (4,4)
    float* out = (float*)d_out;               // (8,128,256,256)

    // units = NC * RYP = 65536 ; warps = 131072 ; threads = 4,194,304
    int threads = 128;
    int blocks = (NC * RYP * 2 * 32) / threads;   // 32768
    Upscale_15358803050749_kernel<<<blocks, threads>>>(x, k, out);
}